// round 9
// baseline (speedup 1.0000x reference)
#include <cuda_runtime.h>
#include <math.h>
#include <stdint.h>

#define D_MODEL   1024
#define N_HEADS   16
#define D_QKV     64
#define D_FF      4096
#define N_LAYERS  6
#define SEQ       1024
#define BATCH     8
#define TOK       (BATCH*SEQ)
#define N_ACTIONS 16

// ---------------- static device scratch ----------------
__device__ float g_h[TOK * D_MODEL];            // residual stream (fp32)
__device__ float g_hr[TOK * D_MODEL];           // tf32-rounded copy of h
__device__ float g_qkv[TOK * 3 * D_MODEL];
__device__ float g_ctx[TOK * D_MODEL];          // tf32-rounded at write
__device__ float g_buf1[TOK * D_FF];
__device__ float g_buf2[TOK * D_MODEL];
// transposed + tf32-rounded weights, [N][K] K-major
__device__ float g_wqkv[N_LAYERS * 3 * D_MODEL * D_MODEL];
__device__ float g_wot [N_LAYERS * D_MODEL * D_MODEL];
__device__ float g_w1t [N_LAYERS * D_FF * D_MODEL];
__device__ float g_w2t [N_LAYERS * D_MODEL * D_FF];

// tf32 round-to-nearest-even via integer ops (proven in R8).
__device__ __forceinline__ float tf32i(float x) {
    uint32_t u = __float_as_uint(x);
    u = (u + 0x00000FFFu + ((u >> 13) & 1u)) & 0xFFFFE000u;
    return __uint_as_float(u);
}

__device__ __forceinline__ void mma_tf32(float* c, const uint32_t* a, const uint32_t* b) {
    asm volatile(
        "mma.sync.aligned.m16n8k8.row.col.f32.tf32.tf32.f32 "
        "{%0,%1,%2,%3}, {%4,%5,%6,%7}, {%8,%9}, {%0,%1,%2,%3};"
        : "+f"(c[0]), "+f"(c[1]), "+f"(c[2]), "+f"(c[3])
        : "r"(a[0]), "r"(a[1]), "r"(a[2]), "r"(a[3]), "r"(b[0]), "r"(b[1]));
}

__device__ __forceinline__ void cpa16(void* dst, const void* src) {
    uint32_t d;
    asm("{ .reg .u64 t; cvta.to.shared.u64 t, %1; cvt.u32.u64 %0, t; }" : "=r"(d) : "l"(dst));
    asm volatile("cp.async.cg.shared.global [%0], [%1], 16;" :: "r"(d), "l"(src));
}
#define CP_COMMIT() asm volatile("cp.async.commit_group;" ::: "memory")
#define CP_WAIT1()  asm volatile("cp.async.wait_group 1;" ::: "memory")
#define CP_WAIT0()  asm volatile("cp.async.wait_group 0;" ::: "memory")

// ---------------- embedding + positional encoding ----------------
__global__ void embed_kernel(const int* __restrict__ x, const float* __restrict__ embed)
{
    int t   = blockIdx.x;
    int tid = threadIdx.x;
    int l   = t & (SEQ - 1);
    int tok = x[t];
    int j   = tid * 4;

    float4 ev = *(const float4*)(embed + (size_t)tok * D_MODEL + j);
    float pos = (float)(l + 1);
    float ang0 = pos / powf(10000.0f, (float)j       * (1.0f / D_MODEL));
    float ang1 = pos / powf(10000.0f, (float)(j + 2) * (1.0f / D_MODEL));

    float4 o;
    o.x = ev.x * 32.0f + sinf(ang0);
    o.y = ev.y * 32.0f + cosf(ang0);
    o.z = ev.z * 32.0f + sinf(ang1);
    o.w = ev.w * 32.0f + cosf(ang1);
    *(float4*)(g_h + (size_t)t * D_MODEL + j) = o;
    float4 r = make_float4(tf32i(o.x), tf32i(o.y), tf32i(o.z), tf32i(o.w));
    *(float4*)(g_hr + (size_t)t * D_MODEL + j) = r;
}

// ---------------- weight transposes: dst[n][k] = tf32round(src[k][n]) ----------------
__global__ void tposew_kernel(const float* __restrict__ src, float* __restrict__ dst,
                              int R, int C, size_t sstride, size_t dstride)
{
    __shared__ float t[32][33];
    int z = blockIdx.z;
    src += (size_t)z * sstride;
    dst += (size_t)z * dstride;
    int c0 = blockIdx.x * 32, r0 = blockIdx.y * 32;
    int tx = threadIdx.x, ty = threadIdx.y;   // 32 x 8
    #pragma unroll
    for (int i = 0; i < 32; i += 8)
        t[ty + i][tx] = src[(size_t)(r0 + ty + i) * C + c0 + tx];
    __syncthreads();
    #pragma unroll
    for (int i = 0; i < 32; i += 8)
        dst[(size_t)(c0 + ty + i) * R + r0 + tx] = tf32i(t[tx][ty + i]);
}

// QKV pack: g_wqkv[l][sel*1024 + h*64 + d][k] = tf32round(W[l][h][k][d])
__global__ void tposeqkv_kernel(const float* __restrict__ Wq, const float* __restrict__ Wk,
                                const float* __restrict__ Wv)
{
    __shared__ float t[32][33];
    int z = blockIdx.z;            // l*48 + sel*16 + h
    int l = z / 48, rem = z % 48, sel = rem >> 4, h = rem & 15;
    const float* W = (sel == 0) ? Wq : (sel == 1) ? Wk : Wv;
    const float* src = W + ((size_t)(l * 16 + h)) * D_MODEL * D_QKV;   // [1024 k][64 d]
    float* dst = g_wqkv + (size_t)l * 3 * D_MODEL * D_MODEL
               + (size_t)(sel * 1024 + h * 64) * D_MODEL;              // [d][k]
    int c0 = blockIdx.x * 32, r0 = blockIdx.y * 32;                    // C=64, R=1024
    int tx = threadIdx.x, ty = threadIdx.y;
    #pragma unroll
    for (int i = 0; i < 32; i += 8)
        t[ty + i][tx] = src[(size_t)(r0 + ty + i) * 64 + c0 + tx];
    __syncthreads();
    #pragma unroll
    for (int i = 0; i < 32; i += 8)
        dst[(size_t)(c0 + ty + i) * D_MODEL + r0 + tx] = tf32i(t[tx][ty + i]);
}

// ---------------- tensor-core GEMM via mma.sync tf32 + cp.async ----------------
// C[M,N] = A[M,K] @ Bt[N,K]^T.  CTA 128x128, 8 warps (4m x 2n), warp 32x64,
// BK=16 (two k8 steps). 2-stage cp.async double buffer.
// Inputs (A and Bt) must already be tf32-rounded by their producers.
#define FLG_RELU 1
#define FLG_RND  2

__global__ void __launch_bounds__(256)
tgemm_kernel(const float* __restrict__ A, const float* __restrict__ Bt,
             const float* __restrict__ bias, float* __restrict__ C,
             int M, int N, int K, int flags)
{
    __shared__ float As[2][128][20];   // 10240 B per stage
    __shared__ float Bs[2][128][20];   // total 40960 B static

    const int tid  = threadIdx.x;
    const int wid  = tid >> 5;
    const int lane = tid & 31;
    const int grp  = lane >> 2;         // 0..7
    const int qid  = lane & 3;          // 0..3
    const int wm   = (wid >> 1) * 32;   // 4 m-warps
    const int wn   = (wid & 1) * 64;    // 2 n-warps

    const float* Ab = A  + (size_t)blockIdx.y * 128 * K;
    const float* Bb = Bt + (size_t)blockIdx.x * 128 * K;

    const int lrow = tid >> 1;          // 0..127
    const int lcol = (tid & 1) * 8;     // 0 or 8

    float acc[2][8][4];
    #pragma unroll
    for (int mt = 0; mt < 2; mt++)
        #pragma unroll
        for (int nt = 0; nt < 8; nt++)
            #pragma unroll
            for (int i = 0; i < 4; i++) acc[mt][nt][i] = 0.0f;

    #define LOAD_CHUNK(cc, st) do {                                        \
        int _k0 = (cc) << 4;                                               \
        cpa16(&As[st][lrow][lcol],     Ab + (size_t)lrow * K + _k0 + lcol);        \
        cpa16(&As[st][lrow][lcol + 4], Ab + (size_t)lrow * K + _k0 + lcol + 4);    \
        cpa16(&Bs[st][lrow][lcol],     Bb + (size_t)lrow * K + _k0 + lcol);        \
        cpa16(&Bs[st][lrow][lcol + 4], Bb + (size_t)lrow * K + _k0 + lcol + 4);    \
        CP_COMMIT();                                                       \
    } while (0)

    LOAD_CHUNK(0, 0);

    const int CH = K >> 4;
    for (int c = 0; c < CH; c++) {
        int s = c & 1;
        if (c + 1 < CH) {
            LOAD_CHUNK(c + 1, s ^ 1);   // overlaps with this chunk's MMA
            CP_WAIT1();                 // chunk c's group complete
        } else {
            CP_WAIT0();
        }
        __syncthreads();                // stage s visible to all threads

        #pragma unroll
        for (int ks = 0; ks < 16; ks += 8) {
            uint32_t a[2][4], b[8][2];
            #pragma unroll
            for (int mt = 0; mt < 2; mt++) {
                int r = wm + mt * 16 + grp;
                a[mt][0] = __float_as_uint(As[s][r][ks + qid]);
                a[mt][1] = __float_as_uint(As[s][r + 8][ks + qid]);
                a[mt][2] = __float_as_uint(As[s][r][ks + qid + 4]);
                a[mt][3] = __float_as_uint(As[s][r + 8][ks + qid + 4]);
            }
            #pragma unroll
            for (int nt = 0; nt < 8; nt++) {
                int n = wn + nt * 8 + grp;
                b[nt][0] = __float_as_uint(Bs[s][n][ks + qid]);
                b[nt][1] = __float_as_uint(Bs[s][n][ks + qid + 4]);
            }
            #pragma unroll
            for (int mt = 0; mt < 2; mt++)
                #pragma unroll
                for (int nt = 0; nt < 8; nt++)
                    mma_tf32(acc[mt][nt], a[mt], b[nt]);
        }
        __syncthreads();                // all reads done before next overwrite
    }

    // epilogue: c0,c1 -> (row, 2q),(row, 2q+1); c2,c3 -> row+8
    const bool relu = (flags & FLG_RELU) != 0;
    const bool rnd  = (flags & FLG_RND)  != 0;
    #pragma unroll
    for (int mt = 0; mt < 2; mt++) {
        #pragma unroll
        for (int nt = 0; nt < 8; nt++) {
            int row = blockIdx.y * 128 + wm + mt * 16 + grp;
            int col = blockIdx.x * 128 + wn + nt * 8 + qid * 2;
            float v0 = acc[mt][nt][0], v1 = acc[mt][nt][1];
            float v2 = acc[mt][nt][2], v3 = acc[mt][nt][3];
            if (bias) {
                float b0 = bias[col], b1 = bias[col + 1];
                v0 += b0; v1 += b1; v2 += b0; v3 += b1;
            }
            if (relu) {
                v0 = fmaxf(v0, 0.0f); v1 = fmaxf(v1, 0.0f);
                v2 = fmaxf(v2, 0.0f); v3 = fmaxf(v3, 0.0f);
            }
            if (rnd) { v0 = tf32i(v0); v1 = tf32i(v1); v2 = tf32i(v2); v3 = tf32i(v3); }
            *(float2*)(C + (size_t)row * N + col)       = make_float2(v0, v1);
            *(float2*)(C + (size_t)(row + 8) * N + col) = make_float2(v2, v3);
        }
    }
}

// ---------------- fused attention: 256 threads, 2 threads per query ----------------
// thread pair (2q, 2q+1): lane hf = tid&1 owns 32 of the 64 head dims.
// Dot combined via shfl_xor(.,1) -> bit-identical s in both lanes.
#define AQ 128
#define AK 64
__global__ void __launch_bounds__(256)
attn_kernel(const int* __restrict__ mask)
{
    __shared__ float Ks[AK][D_QKV];          // 16 KB
    __shared__ float Vs[AK][D_QKV];          // 16 KB
    __shared__ unsigned char Ms[AK][132];    // [j][query], padded: conflict-free reads

    const int tid  = threadIdx.x;
    const int qi   = tid >> 1;               // query within tile, 0..127
    const int hf   = tid & 1;                // dim half
    const int bh   = blockIdx.y;
    const int b    = bh >> 4;
    const int h    = bh & 15;
    const int q0   = blockIdx.x * AQ;
    const int qrow = q0 + qi;

    const float* qp = g_qkv + (size_t)(b * SEQ + qrow) * (3 * D_MODEL) + h * 64 + hf * 32;
    float q[32];
    #pragma unroll
    for (int i = 0; i < 8; i++) {
        float4 v = *(const float4*)(qp + i * 4);
        q[i*4+0] = v.x; q[i*4+1] = v.y; q[i*4+2] = v.z; q[i*4+3] = v.w;
    }
    float acc[32];
    #pragma unroll
    for (int i = 0; i < 32; i++) acc[i] = 0.0f;
    float m_run = -1e30f, l_run = 0.0f;

    const int* mb = mask + (size_t)b * SEQ * SEQ;

    for (int j0 = 0; j0 < SEQ; j0 += AK) {
        // K/V tiles: 64 rows x 64 floats each; 4 float4-pairs per thread
        #pragma unroll
        for (int it = 0; it < 4; it++) {
            int idx = tid + it * 256;        // 0..1023
            int r = idx >> 4;
            int c = (idx & 15) << 2;
            const float* kp = g_qkv + (size_t)(b * SEQ + j0 + r) * (3 * D_MODEL) + D_MODEL + h * 64 + c;
            *(float4*)&Ks[r][c] = *(const float4*)kp;
            *(float4*)&Vs[r][c] = *(const float4*)(kp + D_MODEL);
        }
        // mask tile: transposed store Ms[j][query]
        #pragma unroll
        for (int it = 0; it < 8; it++) {
            int idx = tid + it * 256;        // 0..2047
            int r = idx >> 4;                // query 0..127
            int c = (idx & 15) << 2;         // j 0,4,..,60
            int4 mv = *(const int4*)(mb + (size_t)(q0 + r) * SEQ + j0 + c);
            Ms[c + 0][r] = (unsigned char)(mv.x != 0);
            Ms[c + 1][r] = (unsigned char)(mv.y != 0);
            Ms[c + 2][r] = (unsigned char)(mv.z != 0);
            Ms[c + 3][r] = (unsigned char)(mv.w != 0);
        }
        __syncthreads();

        #pragma unroll 1
        for (int j = 0; j < AK; j++) {
            float sh = 0.0f;
            #pragma unroll
            for (int d4 = 0; d4 < 8; d4++) {
                float4 kv = *(const float4*)&Ks[j][hf * 32 + d4 * 4];
                sh += q[d4*4+0]*kv.x + q[d4*4+1]*kv.y + q[d4*4+2]*kv.z + q[d4*4+3]*kv.w;
            }
            float s = sh + __shfl_xor_sync(0xffffffffu, sh, 1);
            s = Ms[j][qi] ? s * 0.125f : -1e9f;
            if (s > m_run) {
                float corr = __expf(m_run - s);
                m_run = s;
                l_run *= corr;
                #pragma unroll
                for (int d = 0; d < 32; d++) acc[d] *= corr;
            }
            float p = __expf(s - m_run);
            l_run += p;
            #pragma unroll
            for (int d4 = 0; d4 < 8; d4++) {
                float4 vv = *(const float4*)&Vs[j][hf * 32 + d4 * 4];
                acc[d4*4+0] += p * vv.x;
                acc[d4*4+1] += p * vv.y;
                acc[d4*4+2] += p * vv.z;
                acc[d4*4+3] += p * vv.w;
            }
        }
        __syncthreads();
    }

    float inv = 1.0f / l_run;
    float* op = g_ctx + (size_t)(b * SEQ + qrow) * D_MODEL + h * 64 + hf * 32;
    #pragma unroll
    for (int i = 0; i < 8; i++) {
        float4 v;
        v.x = tf32i(acc[i*4+0] * inv); v.y = tf32i(acc[i*4+1] * inv);
        v.z = tf32i(acc[i*4+2] * inv); v.w = tf32i(acc[i*4+3] * inv);
        *(float4*)(op + i * 4) = v;
    }
}

// ---------------- residual add + layernorm (fp32 out + tf32-rounded copy) ----------------
__global__ void ln_kernel(const float* __restrict__ resid, const float* __restrict__ add,
                          const float* __restrict__ sc, const float* __restrict__ bi,
                          float* __restrict__ out, float* __restrict__ outr)
{
    __shared__ float ssum[8], ssq[8];
    int row = blockIdx.x, tid = threadIdx.x;
    int c = tid * 4;
    float4 hv = *(const float4*)(resid + (size_t)row * D_MODEL + c);
    float4 av = *(const float4*)(add   + (size_t)row * D_MODEL + c);
    float4 r = make_float4(hv.x + av.x, hv.y + av.y, hv.z + av.z, hv.w + av.w);
    float s = r.x + r.y + r.z + r.w;
    float qq = r.x*r.x + r.y*r.y + r.z*r.z + r.w*r.w;
    #pragma unroll
    for (int o = 16; o > 0; o >>= 1) {
        s  += __shfl_xor_sync(0xffffffffu, s,  o);
        qq += __shfl_xor_sync(0xffffffffu, qq, o);
    }
    int w = tid >> 5;
    if ((tid & 31) == 0) { ssum[w] = s; ssq[w] = qq; }
    __syncthreads();
    float ts = 0.0f, tq = 0.0f;
    #pragma unroll
    for (int i = 0; i < 8; i++) { ts += ssum[i]; tq += ssq[i]; }
    float mu   = ts * (1.0f / D_MODEL);
    float var  = tq * (1.0f / D_MODEL) - mu * mu;
    float rstd = rsqrtf(var + 1e-5f);
    float4 scv = *(const float4*)(sc + c);
    float4 biv = *(const float4*)(bi + c);
    float4 o;
    o.x = (r.x - mu) * rstd * scv.x + biv.x;
    o.y = (r.y - mu) * rstd * scv.y + biv.y;
    o.z = (r.z - mu) * rstd * scv.z + biv.z;
    o.w = (r.w - mu) * rstd * scv.w + biv.w;
    *(float4*)(out + (size_t)row * D_MODEL + c) = o;
    float4 rr = make_float4(tf32i(o.x), tf32i(o.y), tf32i(o.z), tf32i(o.w));
    *(float4*)(outr + (size_t)row * D_MODEL + c) = rr;
}

// ---------------- final head ----------------
__global__ void head_kernel(const float* __restrict__ ow, const float* __restrict__ ob,
                            float* __restrict__ out)
{
    int tid = threadIdx.x;           // 128 = 8 batches * 16 actions
    int b = tid >> 4, a = tid & 15;
    const float* hr = g_h + ((size_t)b * SEQ + (SEQ - 1)) * D_MODEL;
    float acc = 0.0f;
    for (int k = 0; k < D_MODEL; k++) acc += hr[k] * ow[k * N_ACTIONS + a];
    acc += ob[a];
    float m = acc;
    #pragma unroll
    for (int o = 8; o > 0; o >>= 1) m = fmaxf(m, __shfl_xor_sync(0xffffffffu, m, o, 16));
    float e = expf(acc - m), sum = e;
    #pragma unroll
    for (int o = 8; o > 0; o >>= 1) sum += __shfl_xor_sync(0xffffffffu, sum, o, 16);
    out[b * N_ACTIONS + a] = acc - m - logf(sum);
}

// ---------------- launch ----------------
extern "C" void kernel_launch(void* const* d_in, const int* in_sizes, int n_in,
                              void* d_out, int out_size)
{
    const int*   x     = (const int*)d_in[0];
    const int*   mask  = (const int*)d_in[1];
    const float* embed = (const float*)d_in[2];
    const float* Wq    = (const float*)d_in[3];
    const float* Wk    = (const float*)d_in[4];
    const float* Wv    = (const float*)d_in[5];
    const float* Wo_w  = (const float*)d_in[6];
    const float* Wo_b  = (const float*)d_in[7];
    const float* ln1s  = (const float*)d_in[8];
    const float* ln1b  = (const float*)d_in[9];
    const float* ffw1  = (const float*)d_in[10];
    const float* ffb1  = (const float*)d_in[11];
    const float* ffw2  = (const float*)d_in[12];
    const float* ffb2  = (const float*)d_in[13];
    const float* ln2s  = (const float*)d_in[14];
    const float* ln2b  = (const float*)d_in[15];
    const float* ow    = (const float*)d_in[16];
    const float* ob    = (const float*)d_in[17];
    float* out = (float*)d_out;

    float *h, *hr, *qkv, *ctx, *buf1, *buf2, *wqkv, *wot, *w1t, *w2t;
    cudaGetSymbolAddress((void**)&h,    g_h);
    cudaGetSymbolAddress((void**)&hr,   g_hr);
    cudaGetSymbolAddress((void**)&qkv,  g_qkv);
    cudaGetSymbolAddress((void**)&ctx,  g_ctx);
    cudaGetSymbolAddress((void**)&buf1, g_buf1);
    cudaGetSymbolAddress((void**)&buf2, g_buf2);
    cudaGetSymbolAddress((void**)&wqkv, g_wqkv);
    cudaGetSymbolAddress((void**)&wot,  g_wot);
    cudaGetSymbolAddress((void**)&w1t,  g_w1t);
    cudaGetSymbolAddress((void**)&w2t,  g_w2t);

    // per-launch weight packs (transposed + tf32-rounded)
    dim3 tb(32, 8);
    tposeqkv_kernel<<<dim3(2, 32, N_LAYERS * 48), tb>>>(Wq, Wk, Wv);
    tposew_kernel<<<dim3(32, 32, N_LAYERS), tb>>>(Wo_w, wot, 1024, 1024,
        (size_t)D_MODEL * D_MODEL, (size_t)D_MODEL * D_MODEL);
    tposew_kernel<<<dim3(128, 32, N_LAYERS), tb>>>(ffw1, w1t, 1024, 4096,
        (size_t)D_MODEL * D_FF, (size_t)D_FF * D_MODEL);
    tposew_kernel<<<dim3(32, 128, N_LAYERS), tb>>>(ffw2, w2t, 4096, 1024,
        (size_t)D_FF * D_MODEL, (size_t)D_MODEL * D_FF);

    embed_kernel<<<TOK, 256>>>(x, embed);

    for (int i = 0; i < N_LAYERS; i++) {
        tgemm_kernel<<<dim3((3 * D_MODEL) / 128, TOK / 128), 256>>>(
            hr, wqkv + (size_t)i * 3 * D_MODEL * D_MODEL, nullptr, qkv,
            TOK, 3 * D_MODEL, D_MODEL, 0);
        attn_kernel<<<dim3(SEQ / AQ, BATCH * N_HEADS), 256>>>(mask);
        tgemm_kernel<<<dim3(D_MODEL / 128, TOK / 128), 256>>>(
            ctx, wot + (size_t)i * D_MODEL * D_MODEL, Wo_b + (size_t)i * D_MODEL, buf1,
            TOK, D_MODEL, D_MODEL, 0);
        ln_kernel<<<TOK, 256>>>(h, buf1, ln1s + (size_t)i * D_MODEL, ln1b + (size_t)i * D_MODEL, h, hr);
        tgemm_kernel<<<dim3(D_FF / 128, TOK / 128), 256>>>(
            hr, w1t + (size_t)i * D_FF * D_MODEL, ffb1 + (size_t)i * D_FF, buf1,
            TOK, D_FF, D_MODEL, FLG_RELU | FLG_RND);
        tgemm_kernel<<<dim3(D_MODEL / 128, TOK / 128), 256>>>(
            buf1, w2t + (size_t)i * D_MODEL * D_FF, ffb2 + (size_t)i * D_MODEL, buf2,
            TOK, D_MODEL, D_FF, 0);
        ln_kernel<<<TOK, 256>>>(h, buf2, ln2s + (size_t)i * D_MODEL, ln2b + (size_t)i * D_MODEL, h, hr);
    }

    head_kernel<<<1, 128>>>(ow, ob, out);
}

// round 12
// speedup vs baseline: 1.0840x; 1.0840x over previous
#include <cuda_runtime.h>
#include <cuda_fp16.h>
#include <math.h>
#include <stdint.h>

#define D_MODEL   1024
#define N_HEADS   16
#define D_QKV     64
#define D_FF      4096
#define N_LAYERS  6
#define SEQ       1024
#define BATCH     8
#define TOK       (BATCH*SEQ)
#define N_ACTIONS 16

// ---------------- static device scratch ----------------
__device__ float g_h[TOK * D_MODEL];            // residual stream (fp32)
__device__ float g_qkv[TOK * 3 * D_MODEL];
__device__ float g_ctx[TOK * D_MODEL];
__device__ float g_buf1[TOK * D_FF];
__device__ float g_buf2[TOK * D_MODEL];
// transposed weights, [N][K] K-major (fp32; fp16 conversion happens in GEMM)
__device__ float g_wqkv[N_LAYERS * 3 * D_MODEL * D_MODEL];
__device__ float g_wot [N_LAYERS * D_MODEL * D_MODEL];
__device__ float g_w1t [N_LAYERS * D_FF * D_MODEL];
__device__ float g_w2t [N_LAYERS * D_MODEL * D_FF];

__device__ __forceinline__ uint32_t pack_h2(float lo, float hi) {
    __half2 h = __floats2half2_rn(lo, hi);    // .x = lo -> low 16 bits (smaller k)
    return *reinterpret_cast<uint32_t*>(&h);
}

__device__ __forceinline__ void mma_f16(float* c, const uint32_t* a, const uint32_t* b) {
    asm volatile(
        "mma.sync.aligned.m16n8k16.row.col.f32.f16.f16.f32 "
        "{%0,%1,%2,%3}, {%4,%5,%6,%7}, {%8,%9}, {%0,%1,%2,%3};"
        : "+f"(c[0]), "+f"(c[1]), "+f"(c[2]), "+f"(c[3])
        : "r"(a[0]), "r"(a[1]), "r"(a[2]), "r"(a[3]), "r"(b[0]), "r"(b[1]));
}

// ---------------- embedding + positional encoding ----------------
__global__ void embed_kernel(const int* __restrict__ x, const float* __restrict__ embed)
{
    int t   = blockIdx.x;
    int tid = threadIdx.x;
    int l   = t & (SEQ - 1);
    int tok = x[t];
    int j   = tid * 4;

    float4 ev = *(const float4*)(embed + (size_t)tok * D_MODEL + j);
    float pos = (float)(l + 1);
    float ang0 = pos / powf(10000.0f, (float)j       * (1.0f / D_MODEL));
    float ang1 = pos / powf(10000.0f, (float)(j + 2) * (1.0f / D_MODEL));

    float4 o;
    o.x = ev.x * 32.0f + sinf(ang0);
    o.y = ev.y * 32.0f + cosf(ang0);
    o.z = ev.z * 32.0f + sinf(ang1);
    o.w = ev.w * 32.0f + cosf(ang1);
    *(float4*)(g_h + (size_t)t * D_MODEL + j) = o;
}

// ---------------- weight transposes: dst[n][k] = src[k][n] ----------------
__global__ void tposew_kernel(const float* __restrict__ src, float* __restrict__ dst,
                              int R, int C, size_t sstride, size_t dstride)
{
    __shared__ float t[32][33];
    int z = blockIdx.z;
    src += (size_t)z * sstride;
    dst += (size_t)z * dstride;
    int c0 = blockIdx.x * 32, r0 = blockIdx.y * 32;
    int tx = threadIdx.x, ty = threadIdx.y;   // 32 x 8
    #pragma unroll
    for (int i = 0; i < 32; i += 8)
        t[ty + i][tx] = src[(size_t)(r0 + ty + i) * C + c0 + tx];
    __syncthreads();
    #pragma unroll
    for (int i = 0; i < 32; i += 8)
        dst[(size_t)(c0 + ty + i) * R + r0 + tx] = t[tx][ty + i];
}

// QKV pack: g_wqkv[l][sel*1024 + h*64 + d][k] = W[l][h][k][d]
__global__ void tposeqkv_kernel(const float* __restrict__ Wq, const float* __restrict__ Wk,
                                const float* __restrict__ Wv)
{
    __shared__ float t[32][33];
    int z = blockIdx.z;            // l*48 + sel*16 + h
    int l = z / 48, rem = z % 48, sel = rem >> 4, h = rem & 15;
    const float* W = (sel == 0) ? Wq : (sel == 1) ? Wk : Wv;
    const float* src = W + ((size_t)(l * 16 + h)) * D_MODEL * D_QKV;   // [1024 k][64 d]
    float* dst = g_wqkv + (size_t)l * 3 * D_MODEL * D_MODEL
               + (size_t)(sel * 1024 + h * 64) * D_MODEL;              // [d][k]
    int c0 = blockIdx.x * 32, r0 = blockIdx.y * 32;                    // C=64, R=1024
    int tx = threadIdx.x, ty = threadIdx.y;
    #pragma unroll
    for (int i = 0; i < 32; i += 8)
        t[ty + i][tx] = src[(size_t)(r0 + ty + i) * 64 + c0 + tx];
    __syncthreads();
    #pragma unroll
    for (int i = 0; i < 32; i += 8)
        dst[(size_t)(c0 + ty + i) * D_MODEL + r0 + tx] = t[tx][ty + i];
}

// ---------------- tensor-core GEMM via mma.sync fp16 (m16n8k16) ----------------
// C[M,N] = A[M,K] @ Bt[N,K]^T, fp32 in/out, fp16 operands (round at STS).
// CTA 128x128, 8 warps (4m x 2n), warp 32x64, chunk K=32 (two k16 steps).
// SMEM rows: 32 halves padded to 40 (20 words, stride-20 -> conflict-free).
#define FLG_RELU 1

__global__ void __launch_bounds__(256)
tgemm_kernel(const float* __restrict__ A, const float* __restrict__ Bt,
             const float* __restrict__ bias, float* __restrict__ C,
             int M, int N, int K, int flags)
{
    __shared__ __align__(16) uint32_t As[2][128][20];   // 10240 B per stage
    __shared__ __align__(16) uint32_t Bs[2][128][20];   // total 40960 B

    const int tid  = threadIdx.x;
    const int wid  = tid >> 5;
    const int lane = tid & 31;
    const int grp  = lane >> 2;         // 0..7
    const int qid  = lane & 3;          // 0..3
    const int wm   = (wid >> 1) * 32;   // 4 m-warps
    const int wn   = (wid & 1) * 64;    // 2 n-warps

    const float* Ab = A  + (size_t)blockIdx.y * 128 * K;
    const float* Bb = Bt + (size_t)blockIdx.x * 128 * K;

    const int lrow  = tid >> 1;         // 0..127
    const int lcolf = (tid & 1) * 16;   // float index within chunk (0 or 16)
    const int lcolw = (tid & 1) * 8;    // word index (0 or 8)

    float acc[2][8][4];
    #pragma unroll
    for (int mt = 0; mt < 2; mt++)
        #pragma unroll
        for (int nt = 0; nt < 8; nt++)
            #pragma unroll
            for (int i = 0; i < 4; i++) acc[mt][nt][i] = 0.0f;

    uint32_t pa[8], pb[8];
    #define FETCH_CHUNK(cc) do {                                                 \
        int _k0 = (cc) << 5;                                                     \
        _Pragma("unroll")                                                        \
        for (int i = 0; i < 4; i++) {                                            \
            float4 fa = *(const float4*)(Ab + (size_t)lrow * K + _k0 + lcolf + i * 4); \
            float4 fb = *(const float4*)(Bb + (size_t)lrow * K + _k0 + lcolf + i * 4); \
            pa[i*2+0] = pack_h2(fa.x, fa.y); pa[i*2+1] = pack_h2(fa.z, fa.w);    \
            pb[i*2+0] = pack_h2(fb.x, fb.y); pb[i*2+1] = pack_h2(fb.z, fb.w);    \
        }                                                                        \
    } while (0)

    #define STORE_CHUNK(st) do {                                                 \
        uint32_t* _da = &As[st][lrow][lcolw];                                    \
        uint32_t* _db = &Bs[st][lrow][lcolw];                                    \
        *(uint4*)_da       = make_uint4(pa[0], pa[1], pa[2], pa[3]);             \
        *(uint4*)(_da + 4) = make_uint4(pa[4], pa[5], pa[6], pa[7]);             \
        *(uint4*)_db       = make_uint4(pb[0], pb[1], pb[2], pb[3]);             \
        *(uint4*)(_db + 4) = make_uint4(pb[4], pb[5], pb[6], pb[7]);             \
    } while (0)

    FETCH_CHUNK(0);
    STORE_CHUNK(0);
    __syncthreads();

    const int CH = K >> 5;
    for (int c = 0; c < CH; c++) {
        int s = c & 1;
        const bool more = (c + 1 < CH);
        if (more) FETCH_CHUNK(c + 1);   // overlaps MMA below

        const uint32_t* Aw = &As[s][0][0];
        const uint32_t* Bw = &Bs[s][0][0];
        #pragma unroll
        for (int ks = 0; ks < 2; ks++) {
            uint32_t a[2][4], b[8][2];
            #pragma unroll
            for (int mt = 0; mt < 2; mt++) {
                int base = (wm + mt * 16 + grp) * 20 + ks * 8 + qid;
                a[mt][0] = Aw[base];
                a[mt][1] = Aw[base + 160];      // row + 8
                a[mt][2] = Aw[base + 4];
                a[mt][3] = Aw[base + 164];
            }
            #pragma unroll
            for (int nt = 0; nt < 8; nt++) {
                int bb = (wn + nt * 8 + grp) * 20 + ks * 8 + qid;
                b[nt][0] = Bw[bb];
                b[nt][1] = Bw[bb + 4];
            }
            #pragma unroll
            for (int mt = 0; mt < 2; mt++)
                #pragma unroll
                for (int nt = 0; nt < 8; nt++)
                    mma_f16(acc[mt][nt], a[mt], b[nt]);
        }

        if (more) {
            __syncthreads();            // all reads of next stage (iter c-1) done
            STORE_CHUNK(s ^ 1);
            __syncthreads();
        }
    }

    // epilogue: c0,c1 -> (row, 2q),(row, 2q+1); c2,c3 -> row+8
    const bool relu = (flags & FLG_RELU) != 0;
    #pragma unroll
    for (int mt = 0; mt < 2; mt++) {
        #pragma unroll
        for (int nt = 0; nt < 8; nt++) {
            int row = blockIdx.y * 128 + wm + mt * 16 + grp;
            int col = blockIdx.x * 128 + wn + nt * 8 + qid * 2;
            float v0 = acc[mt][nt][0], v1 = acc[mt][nt][1];
            float v2 = acc[mt][nt][2], v3 = acc[mt][nt][3];
            if (bias) {
                float b0 = bias[col], b1 = bias[col + 1];
                v0 += b0; v1 += b1; v2 += b0; v3 += b1;
            }
            if (relu) {
                v0 = fmaxf(v0, 0.0f); v1 = fmaxf(v1, 0.0f);
                v2 = fmaxf(v2, 0.0f); v3 = fmaxf(v3, 0.0f);
            }
            *(float2*)(C + (size_t)row * N + col)       = make_float2(v0, v1);
            *(float2*)(C + (size_t)(row + 8) * N + col) = make_float2(v2, v3);
        }
    }
}

// ---------------- fused attention: 256 threads, 2 threads per query ----------------
#define AQ 128
#define AK 64
__global__ void __launch_bounds__(256)
attn_kernel(const int* __restrict__ mask)
{
    __shared__ float Ks[AK][D_QKV];          // 16 KB
    __shared__ float Vs[AK][D_QKV];          // 16 KB
    __shared__ unsigned char Ms[AK][132];    // [j][query], padded

    const int tid  = threadIdx.x;
    const int qi   = tid >> 1;               // query within tile
    const int hf   = tid & 1;                // dim half
    const int bh   = blockIdx.y;
    const int b    = bh >> 4;
    const int h    = bh & 15;
    const int q0   = blockIdx.x * AQ;
    const int qrow = q0 + qi;

    const float* qp = g_qkv + (size_t)(b * SEQ + qrow) * (3 * D_MODEL) + h * 64 + hf * 32;
    float q[32];
    #pragma unroll
    for (int i = 0; i < 8; i++) {
        float4 v = *(const float4*)(qp + i * 4);
        q[i*4+0] = v.x; q[i*4+1] = v.y; q[i*4+2] = v.z; q[i*4+3] = v.w;
    }
    float acc[32];
    #pragma unroll
    for (int i = 0; i < 32; i++) acc[i] = 0.0f;
    float m_run = -1e30f, l_run = 0.0f;

    const int* mb = mask + (size_t)b * SEQ * SEQ;

    for (int j0 = 0; j0 < SEQ; j0 += AK) {
        #pragma unroll
        for (int it = 0; it < 4; it++) {
            int idx = tid + it * 256;
            int r = idx >> 4;
            int c = (idx & 15) << 2;
            const float* kp = g_qkv + (size_t)(b * SEQ + j0 + r) * (3 * D_MODEL) + D_MODEL + h * 64 + c;
            *(float4*)&Ks[r][c] = *(const float4*)kp;
            *(float4*)&Vs[r][c] = *(const float4*)(kp + D_MODEL);
        }
        #pragma unroll
        for (int it = 0; it < 8; it++) {
            int idx = tid + it * 256;
            int r = idx >> 4;
            int c = (idx & 15) << 2;
            int4 mv = *(const int4*)(mb + (size_t)(q0 + r) * SEQ + j0 + c);
            Ms[c + 0][r] = (unsigned char)(mv.x != 0);
            Ms[c + 1][r] = (unsigned char)(mv.y != 0);
            Ms[c + 2][r] = (unsigned char)(mv.z != 0);
            Ms[c + 3][r] = (unsigned char)(mv.w != 0);
        }
        __syncthreads();

        #pragma unroll 1
        for (int j = 0; j < AK; j++) {
            float sh = 0.0f;
            #pragma unroll
            for (int d4 = 0; d4 < 8; d4++) {
                float4 kv = *(const float4*)&Ks[j][hf * 32 + d4 * 4];
                sh += q[d4*4+0]*kv.x + q[d4*4+1]*kv.y + q[d4*4+2]*kv.z + q[d4*4+3]*kv.w;
            }
            float s = sh + __shfl_xor_sync(0xffffffffu, sh, 1);
            s = Ms[j][qi] ? s * 0.125f : -1e9f;
            if (s > m_run) {
                float corr = __expf(m_run - s);
                m_run = s;
                l_run *= corr;
                #pragma unroll
                for (int d = 0; d < 32; d++) acc[d] *= corr;
            }
            float p = __expf(s - m_run);
            l_run += p;
            #pragma unroll
            for (int d4 = 0; d4 < 8; d4++) {
                float4 vv = *(const float4*)&Vs[j][hf * 32 + d4 * 4];
                acc[d4*4+0] += p * vv.x;
                acc[d4*4+1] += p * vv.y;
                acc[d4*4+2] += p * vv.z;
                acc[d4*4+3] += p * vv.w;
            }
        }
        __syncthreads();
    }

    float inv = 1.0f / l_run;
    float* op = g_ctx + (size_t)(b * SEQ + qrow) * D_MODEL + h * 64 + hf * 32;
    #pragma unroll
    for (int i = 0; i < 8; i++) {
        float4 v;
        v.x = acc[i*4+0] * inv; v.y = acc[i*4+1] * inv;
        v.z = acc[i*4+2] * inv; v.w = acc[i*4+3] * inv;
        *(float4*)(op + i * 4) = v;
    }
}

// ---------------- residual add + layernorm ----------------
__global__ void ln_kernel(const float* __restrict__ resid, const float* __restrict__ add,
                          const float* __restrict__ sc, const float* __restrict__ bi,
                          float* __restrict__ out)
{
    __shared__ float ssum[8], ssq[8];
    int row = blockIdx.x, tid = threadIdx.x;
    int c = tid * 4;
    float4 hv = *(const float4*)(resid + (size_t)row * D_MODEL + c);
    float4 av = *(const float4*)(add   + (size_t)row * D_MODEL + c);
    float4 r = make_float4(hv.x + av.x, hv.y + av.y, hv.z + av.z, hv.w + av.w);
    float s = r.x + r.y + r.z + r.w;
    float qq = r.x*r.x + r.y*r.y + r.z*r.z + r.w*r.w;
    #pragma unroll
    for (int o = 16; o > 0; o >>= 1) {
        s  += __shfl_xor_sync(0xffffffffu, s,  o);
        qq += __shfl_xor_sync(0xffffffffu, qq, o);
    }
    int w = tid >> 5;
    if ((tid & 31) == 0) { ssum[w] = s; ssq[w] = qq; }
    __syncthreads();
    float ts = 0.0f, tq = 0.0f;
    #pragma unroll
    for (int i = 0; i < 8; i++) { ts += ssum[i]; tq += ssq[i]; }
    float mu   = ts * (1.0f / D_MODEL);
    float var  = tq * (1.0f / D_MODEL) - mu * mu;
    float rstd = rsqrtf(var + 1e-5f);
    float4 scv = *(const float4*)(sc + c);
    float4 biv = *(const float4*)(bi + c);
    float4 o;
    o.x = (r.x - mu) * rstd * scv.x + biv.x;
    o.y = (r.y - mu) * rstd * scv.y + biv.y;
    o.z = (r.z - mu) * rstd * scv.z + biv.z;
    o.w = (r.w - mu) * rstd * scv.w + biv.w;
    *(float4*)(out + (size_t)row * D_MODEL + c) = o;
}

// ---------------- final head ----------------
__global__ void head_kernel(const float* __restrict__ ow, const float* __restrict__ ob,
                            float* __restrict__ out)
{
    int tid = threadIdx.x;           // 128 = 8 batches * 16 actions
    int b = tid >> 4, a = tid & 15;
    const float* hr = g_h + ((size_t)b * SEQ + (SEQ - 1)) * D_MODEL;
    float acc = 0.0f;
    for (int k = 0; k < D_MODEL; k++) acc += hr[k] * ow[k * N_ACTIONS + a];
    acc += ob[a];
    float m = acc;
    #pragma unroll
    for (int o = 8; o > 0; o >>= 1) m = fmaxf(m, __shfl_xor_sync(0xffffffffu, m, o, 16));
    float e = expf(acc - m), sum = e;
    #pragma unroll
    for (int o = 8; o > 0; o >>= 1) sum += __shfl_xor_sync(0xffffffffu, sum, o, 16);
    out[b * N_ACTIONS + a] = acc - m - logf(sum);
}

// ---------------- launch ----------------
extern "C" void kernel_launch(void* const* d_in, const int* in_sizes, int n_in,
                              void* d_out, int out_size)
{
    const int*   x     = (const int*)d_in[0];
    const int*   mask  = (const int*)d_in[1];
    const float* embed = (const float*)d_in[2];
    const float* Wq    = (const float*)d_in[3];
    const float* Wk    = (const float*)d_in[4];
    const float* Wv    = (const float*)d_in[5];
    const float* Wo_w  = (const float*)d_in[6];
    const float* Wo_b  = (const float*)d_in[7];
    const float* ln1s  = (const float*)d_in[8];
    const float* ln1b  = (const float*)d_in[9];
    const float* ffw1  = (const float*)d_in[10];
    const float* ffb1  = (const float*)d_in[11];
    const float* ffw2  = (const float*)d_in[12];
    const float* ffb2  = (const float*)d_in[13];
    const float* ln2s  = (const float*)d_in[14];
    const float* ln2b  = (const float*)d_in[15];
    const float* ow    = (const float*)d_in[16];
    const float* ob    = (const float*)d_in[17];
    float* out = (float*)d_out;

    float *h, *qkv, *ctx, *buf1, *buf2, *wqkv, *wot, *w1t, *w2t;
    cudaGetSymbolAddress((void**)&h,    g_h);
    cudaGetSymbolAddress((void**)&qkv,  g_qkv);
    cudaGetSymbolAddress((void**)&ctx,  g_ctx);
    cudaGetSymbolAddress((void**)&buf1, g_buf1);
    cudaGetSymbolAddress((void**)&buf2, g_buf2);
    cudaGetSymbolAddress((void**)&wqkv, g_wqkv);
    cudaGetSymbolAddress((void**)&wot,  g_wot);
    cudaGetSymbolAddress((void**)&w1t,  g_w1t);
    cudaGetSymbolAddress((void**)&w2t,  g_w2t);

    // per-launch weight packs (transposed)
    dim3 tb(32, 8);
    tposeqkv_kernel<<<dim3(2, 32, N_LAYERS * 48), tb>>>(Wq, Wk, Wv);
    tposew_kernel<<<dim3(32, 32, N_LAYERS), tb>>>(Wo_w, wot, 1024, 1024,
        (size_t)D_MODEL * D_MODEL, (size_t)D_MODEL * D_MODEL);
    tposew_kernel<<<dim3(128, 32, N_LAYERS), tb>>>(ffw1, w1t, 1024, 4096,
        (size_t)D_MODEL * D_FF, (size_t)D_FF * D_MODEL);
    tposew_kernel<<<dim3(32, 128, N_LAYERS), tb>>>(ffw2, w2t, 4096, 1024,
        (size_t)D_FF * D_MODEL, (size_t)D_MODEL * D_FF);

    embed_kernel<<<TOK, 256>>>(x, embed);

    for (int i = 0; i < N_LAYERS; i++) {
        tgemm_kernel<<<dim3((3 * D_MODEL) / 128, TOK / 128), 256>>>(
            h, wqkv + (size_t)i * 3 * D_MODEL * D_MODEL, nullptr, qkv,
            TOK, 3 * D_MODEL, D_MODEL, 0);
        attn_kernel<<<dim3(SEQ / AQ, BATCH * N_HEADS), 256>>>(mask);
        tgemm_kernel<<<dim3(D_MODEL / 128, TOK / 128), 256>>>(
            ctx, wot + (size_t)i * D_MODEL * D_MODEL, Wo_b + (size_t)i * D_MODEL, buf1,
            TOK, D_MODEL, D_MODEL, 0);
        ln_kernel<<<TOK, 256>>>(h, buf1, ln1s + (size_t)i * D_MODEL, ln1b + (size_t)i * D_MODEL, h);
        tgemm_kernel<<<dim3(D_FF / 128, TOK / 128), 256>>>(
            h, w1t + (size_t)i * D_FF * D_MODEL, ffb1 + (size_t)i * D_FF, buf1,
            TOK, D_FF, D_MODEL, FLG_RELU);
        tgemm_kernel<<<dim3(D_MODEL / 128, TOK / 128), 256>>>(
            buf1, w2t + (size_t)i * D_MODEL * D_FF, ffb2 + (size_t)i * D_MODEL, buf2,
            TOK, D_MODEL, D_FF, 0);
        ln_kernel<<<TOK, 256>>>(h, buf2, ln2s + (size_t)i * D_MODEL, ln2b + (size_t)i * D_MODEL, h);
    }

    head_kernel<<<1, 128>>>(ow, ob, out);
}

// round 14
// speedup vs baseline: 1.2120x; 1.1181x over previous
#include <cuda_runtime.h>
#include <cuda_fp16.h>
#include <math.h>
#include <stdint.h>

#define D_MODEL   1024
#define N_HEADS   16
#define D_QKV     64
#define D_FF      4096
#define N_LAYERS  6
#define SEQ       1024
#define BATCH     8
#define TOK       (BATCH*SEQ)
#define N_ACTIONS 16

// ---------------- static device scratch ----------------
__device__ float  g_h   [TOK * D_MODEL];        // residual stream fp32
__device__ __half g_h16 [TOK * D_MODEL];        // half copy (GEMM A operand)
__device__ __half g_qkv [TOK * 3 * D_MODEL];    // QKV (half)
__device__ __half g_ctx [TOK * D_MODEL];        // attention out (half)
__device__ __half g_mid [TOK * D_FF];           // FF mid (half)
__device__ float  g_bufa[TOK * D_MODEL];        // att_out fp32 (residual add)
__device__ float  g_bufb[TOK * D_MODEL];        // ff out fp32 (residual add)
// transposed weights, [N][K] K-major, half
__device__ __half g_wqkv[N_LAYERS * 3 * D_MODEL * D_MODEL];
__device__ __half g_wot [N_LAYERS * D_MODEL * D_MODEL];
__device__ __half g_w1t [N_LAYERS * D_FF * D_MODEL];
__device__ __half g_w2t [N_LAYERS * D_MODEL * D_FF];

__device__ __forceinline__ void mma_f16(float* c, const uint32_t* a, const uint32_t* b) {
    asm volatile(
        "mma.sync.aligned.m16n8k16.row.col.f32.f16.f16.f32 "
        "{%0,%1,%2,%3}, {%4,%5,%6,%7}, {%8,%9}, {%0,%1,%2,%3};"
        : "+f"(c[0]), "+f"(c[1]), "+f"(c[2]), "+f"(c[3])
        : "r"(a[0]), "r"(a[1]), "r"(a[2]), "r"(a[3]), "r"(b[0]), "r"(b[1]));
}

// ---------------- embedding + positional encoding ----------------
__global__ void embed_kernel(const int* __restrict__ x, const float* __restrict__ embed)
{
    int t   = blockIdx.x;
    int tid = threadIdx.x;
    int l   = t & (SEQ - 1);
    int tok = x[t];
    int j   = tid * 4;

    float4 ev = *(const float4*)(embed + (size_t)tok * D_MODEL + j);
    float pos = (float)(l + 1);
    float ang0 = pos / powf(10000.0f, (float)j       * (1.0f / D_MODEL));
    float ang1 = pos / powf(10000.0f, (float)(j + 2) * (1.0f / D_MODEL));

    float4 o;
    o.x = ev.x * 32.0f + sinf(ang0);
    o.y = ev.y * 32.0f + cosf(ang0);
    o.z = ev.z * 32.0f + sinf(ang1);
    o.w = ev.w * 32.0f + cosf(ang1);
    *(float4*)(g_h + (size_t)t * D_MODEL + j) = o;
    __half2* hp = (__half2*)(g_h16 + (size_t)t * D_MODEL + j);
    hp[0] = __floats2half2_rn(o.x, o.y);
    hp[1] = __floats2half2_rn(o.z, o.w);
}

// ---------------- weight transposes: dst[n][k] = half(src[k][n]) ----------------
__global__ void tposew_kernel(const float* __restrict__ src, __half* __restrict__ dst,
                              int R, int C, size_t sstride, size_t dstride)
{
    __shared__ float t[32][33];
    int z = blockIdx.z;
    src += (size_t)z * sstride;
    dst += (size_t)z * dstride;
    int c0 = blockIdx.x * 32, r0 = blockIdx.y * 32;
    int tx = threadIdx.x, ty = threadIdx.y;   // 32 x 8
    #pragma unroll
    for (int i = 0; i < 32; i += 8)
        t[ty + i][tx] = src[(size_t)(r0 + ty + i) * C + c0 + tx];
    __syncthreads();
    #pragma unroll
    for (int i = 0; i < 32; i += 8)
        dst[(size_t)(c0 + ty + i) * R + r0 + tx] = __float2half(t[tx][ty + i]);
}

__global__ void tposeqkv_kernel(const float* __restrict__ Wq, const float* __restrict__ Wk,
                                const float* __restrict__ Wv)
{
    __shared__ float t[32][33];
    int z = blockIdx.z;            // l*48 + sel*16 + h
    int l = z / 48, rem = z % 48, sel = rem >> 4, h = rem & 15;
    const float* W = (sel == 0) ? Wq : (sel == 1) ? Wk : Wv;
    const float* src = W + ((size_t)(l * 16 + h)) * D_MODEL * D_QKV;   // [1024 k][64 d]
    __half* dst = g_wqkv + (size_t)l * 3 * D_MODEL * D_MODEL
                + (size_t)(sel * 1024 + h * 64) * D_MODEL;             // [d][k]
    int c0 = blockIdx.x * 32, r0 = blockIdx.y * 32;                    // C=64, R=1024
    int tx = threadIdx.x, ty = threadIdx.y;
    #pragma unroll
    for (int i = 0; i < 32; i += 8)
        t[ty + i][tx] = src[(size_t)(r0 + ty + i) * 64 + c0 + tx];
    __syncthreads();
    #pragma unroll
    for (int i = 0; i < 32; i += 8)
        dst[(size_t)(c0 + ty + i) * D_MODEL + r0 + tx] = __float2half(t[tx][ty + i]);
}

// ---------------- tensor-core GEMM: fp16 operands (R12-proven core) ----------------
// C[M,N] = A[M,K] @ Bt[N,K]^T, half in GMEM, fp32 accum.
// CTA 128x128, 8 warps (4m x 2n), warp 32x64, chunk K=32 halves (two k16 steps).
// SMEM words [128][20] per stage: 16 data words padded to 20 -> conflict-free.
#define FLG_RELU 1

__global__ void __launch_bounds__(256)
tgemm_kernel(const __half* __restrict__ A, const __half* __restrict__ Bt,
             const float* __restrict__ bias, float* __restrict__ Cf,
             __half* __restrict__ Ch, int M, int N, int K, int flags)
{
    __shared__ __align__(16) uint32_t As[2][128][20];   // 10240 B per stage
    __shared__ __align__(16) uint32_t Bs[2][128][20];   // total 40960 B

    const int tid  = threadIdx.x;
    const int wid  = tid >> 5;
    const int lane = tid & 31;
    const int grp  = lane >> 2;         // 0..7
    const int qid  = lane & 3;          // 0..3
    const int wm   = (wid >> 1) * 32;   // 4 m-warps
    const int wn   = (wid & 1) * 64;    // 2 n-warps

    const __half* Ab = A  + (size_t)blockIdx.y * 128 * K;
    const __half* Bb = Bt + (size_t)blockIdx.x * 128 * K;

    const int lrow  = tid >> 1;         // 0..127
    const int lcolh = (tid & 1) * 16;   // half index within chunk (0 or 16)
    const int lcolw = (tid & 1) * 8;    // word index (0 or 8)

    float acc[2][8][4];
    #pragma unroll
    for (int mt = 0; mt < 2; mt++)
        #pragma unroll
        for (int nt = 0; nt < 8; nt++)
            #pragma unroll
            for (int i = 0; i < 4; i++) acc[mt][nt][i] = 0.0f;

    uint4 pa0, pa1, pb0, pb1;
    #define FETCH_CHUNK(cc) do {                                                 \
        int _k0 = ((cc) << 5) + lcolh;                                           \
        pa0 = *(const uint4*)(Ab + (size_t)lrow * K + _k0);                      \
        pa1 = *(const uint4*)(Ab + (size_t)lrow * K + _k0 + 8);                  \
        pb0 = *(const uint4*)(Bb + (size_t)lrow * K + _k0);                      \
        pb1 = *(const uint4*)(Bb + (size_t)lrow * K + _k0 + 8);                  \
    } while (0)

    #define STORE_CHUNK(st) do {                                                 \
        *(uint4*)&As[st][lrow][lcolw]     = pa0;                                 \
        *(uint4*)&As[st][lrow][lcolw + 4] = pa1;                                 \
        *(uint4*)&Bs[st][lrow][lcolw]     = pb0;                                 \
        *(uint4*)&Bs[st][lrow][lcolw + 4] = pb1;                                 \
    } while (0)

    FETCH_CHUNK(0);
    STORE_CHUNK(0);
    __syncthreads();

    const int CH = K >> 5;
    for (int c = 0; c < CH; c++) {
        int s = c & 1;
        const bool more = (c + 1 < CH);
        if (more) FETCH_CHUNK(c + 1);   // overlaps MMA below

        const uint32_t* Aw = &As[s][0][0];
        const uint32_t* Bw = &Bs[s][0][0];
        #pragma unroll
        for (int ks = 0; ks < 2; ks++) {
            uint32_t a[2][4], b[8][2];
            #pragma unroll
            for (int mt = 0; mt < 2; mt++) {
                int base = (wm + mt * 16 + grp) * 20 + ks * 8 + qid;
                a[mt][0] = Aw[base];
                a[mt][1] = Aw[base + 160];      // row + 8
                a[mt][2] = Aw[base + 4];
                a[mt][3] = Aw[base + 164];
            }
            #pragma unroll
            for (int nt = 0; nt < 8; nt++) {
                int bb = (wn + nt * 8 + grp) * 20 + ks * 8 + qid;
                b[nt][0] = Bw[bb];
                b[nt][1] = Bw[bb + 4];
            }
            #pragma unroll
            for (int mt = 0; mt < 2; mt++)
                #pragma unroll
                for (int nt = 0; nt < 8; nt++)
                    mma_f16(acc[mt][nt], a[mt], b[nt]);
        }

        if (more) {
            __syncthreads();            // all reads of next stage (iter c-1) done
            STORE_CHUNK(s ^ 1);
            __syncthreads();
        }
    }

    // epilogue: c0,c1 -> (row, 2q),(row, 2q+1); c2,c3 -> row+8
    const bool relu = (flags & FLG_RELU) != 0;
    #pragma unroll
    for (int mt = 0; mt < 2; mt++) {
        #pragma unroll
        for (int nt = 0; nt < 8; nt++) {
            int row = blockIdx.y * 128 + wm + mt * 16 + grp;
            int col = blockIdx.x * 128 + wn + nt * 8 + qid * 2;
            float v0 = acc[mt][nt][0], v1 = acc[mt][nt][1];
            float v2 = acc[mt][nt][2], v3 = acc[mt][nt][3];
            if (bias) {
                float b0 = bias[col], b1 = bias[col + 1];
                v0 += b0; v1 += b1; v2 += b0; v3 += b1;
            }
            if (relu) {
                v0 = fmaxf(v0, 0.0f); v1 = fmaxf(v1, 0.0f);
                v2 = fmaxf(v2, 0.0f); v3 = fmaxf(v3, 0.0f);
            }
            if (Cf) {
                *(float2*)(Cf + (size_t)row * N + col)       = make_float2(v0, v1);
                *(float2*)(Cf + (size_t)(row + 8) * N + col) = make_float2(v2, v3);
            }
            if (Ch) {
                *(__half2*)(Ch + (size_t)row * N + col)       = __floats2half2_rn(v0, v1);
                *(__half2*)(Ch + (size_t)(row + 8) * N + col) = __floats2half2_rn(v2, v3);
            }
        }
    }
}

// ---------------- fused attention: 256 threads, 2 threads per query ----------------
#define AQ 128
#define AK 64
__global__ void __launch_bounds__(256)
attn_kernel(const int* __restrict__ mask)
{
    __shared__ float Ks[AK][D_QKV];          // 16 KB
    __shared__ float Vs[AK][D_QKV];          // 16 KB
    __shared__ unsigned char Ms[AK][132];    // [j][query], padded

    const int tid  = threadIdx.x;
    const int qi   = tid >> 1;               // query within tile
    const int hf   = tid & 1;                // dim half
    const int bh   = blockIdx.y;
    const int b    = bh >> 4;
    const int h    = bh & 15;
    const int q0   = blockIdx.x * AQ;
    const int qrow = q0 + qi;

    const __half2* qp = (const __half2*)(g_qkv + (size_t)(b * SEQ + qrow) * (3 * D_MODEL) + h * 64 + hf * 32);
    float q[32];
    #pragma unroll
    for (int i = 0; i < 16; i++) {
        float2 v = __half22float2(qp[i]);
        q[i*2+0] = v.x; q[i*2+1] = v.y;
    }
    float acc[32];
    #pragma unroll
    for (int i = 0; i < 32; i++) acc[i] = 0.0f;
    float m_run = -1e30f, l_run = 0.0f;

    const int* mb = mask + (size_t)b * SEQ * SEQ;

    for (int j0 = 0; j0 < SEQ; j0 += AK) {
        #pragma unroll
        for (int it = 0; it < 4; it++) {
            int idx = tid + it * 256;        // 0..1023
            int r = idx >> 4;
            int c = (idx & 15) << 2;
            const __half2* kp = (const __half2*)(g_qkv + (size_t)(b * SEQ + j0 + r) * (3 * D_MODEL) + D_MODEL + h * 64 + c);
            const __half2* vp = (const __half2*)(g_qkv + (size_t)(b * SEQ + j0 + r) * (3 * D_MODEL) + 2 * D_MODEL + h * 64 + c);
            float2 k0f = __half22float2(kp[0]), k1f = __half22float2(kp[1]);
            float2 v0f = __half22float2(vp[0]), v1f = __half22float2(vp[1]);
            *(float4*)&Ks[r][c] = make_float4(k0f.x, k0f.y, k1f.x, k1f.y);
            *(float4*)&Vs[r][c] = make_float4(v0f.x, v0f.y, v1f.x, v1f.y);
        }
        #pragma unroll
        for (int it = 0; it < 8; it++) {
            int idx = tid + it * 256;
            int r = idx >> 4;
            int c = (idx & 15) << 2;
            int4 mv = *(const int4*)(mb + (size_t)(q0 + r) * SEQ + j0 + c);
            Ms[c + 0][r] = (unsigned char)(mv.x != 0);
            Ms[c + 1][r] = (unsigned char)(mv.y != 0);
            Ms[c + 2][r] = (unsigned char)(mv.z != 0);
            Ms[c + 3][r] = (unsigned char)(mv.w != 0);
        }
        __syncthreads();

        #pragma unroll 1
        for (int j = 0; j < AK; j++) {
            float sh = 0.0f;
            #pragma unroll
            for (int d4 = 0; d4 < 8; d4++) {
                float4 kv = *(const float4*)&Ks[j][hf * 32 + d4 * 4];
                sh += q[d4*4+0]*kv.x + q[d4*4+1]*kv.y + q[d4*4+2]*kv.z + q[d4*4+3]*kv.w;
            }
            float s = sh + __shfl_xor_sync(0xffffffffu, sh, 1);
            s = Ms[j][qi] ? s * 0.125f : -1e9f;
            if (s > m_run) {
                float corr = __expf(m_run - s);
                m_run = s;
                l_run *= corr;
                #pragma unroll
                for (int d = 0; d < 32; d++) acc[d] *= corr;
            }
            float p = __expf(s - m_run);
            l_run += p;
            #pragma unroll
            for (int d4 = 0; d4 < 8; d4++) {
                float4 vv = *(const float4*)&Vs[j][hf * 32 + d4 * 4];
                acc[d4*4+0] += p * vv.x;
                acc[d4*4+1] += p * vv.y;
                acc[d4*4+2] += p * vv.z;
                acc[d4*4+3] += p * vv.w;
            }
        }
        __syncthreads();
    }

    float inv = 1.0f / l_run;
    __half2* op = (__half2*)(g_ctx + (size_t)(b * SEQ + qrow) * D_MODEL + h * 64 + hf * 32);
    #pragma unroll
    for (int i = 0; i < 16; i++)
        op[i] = __floats2half2_rn(acc[i*2+0] * inv, acc[i*2+1] * inv);
}

// ---------------- residual add + layernorm (fp32 out + half copy) ----------------
__global__ void ln_kernel(const float* __restrict__ resid, const float* __restrict__ add,
                          const float* __restrict__ sc, const float* __restrict__ bi,
                          float* __restrict__ out, __half* __restrict__ outh)
{
    __shared__ float ssum[8], ssq[8];
    int row = blockIdx.x, tid = threadIdx.x;
    int c = tid * 4;
    float4 hv = *(const float4*)(resid + (size_t)row * D_MODEL + c);
    float4 av = *(const float4*)(add   + (size_t)row * D_MODEL + c);
    float4 r = make_float4(hv.x + av.x, hv.y + av.y, hv.z + av.z, hv.w + av.w);
    float s = r.x + r.y + r.z + r.w;
    float qq = r.x*r.x + r.y*r.y + r.z*r.z + r.w*r.w;
    #pragma unroll
    for (int o = 16; o > 0; o >>= 1) {
        s  += __shfl_xor_sync(0xffffffffu, s,  o);
        qq += __shfl_xor_sync(0xffffffffu, qq, o);
    }
    int w = tid >> 5;
    if ((tid & 31) == 0) { ssum[w] = s; ssq[w] = qq; }
    __syncthreads();
    float ts = 0.0f, tq = 0.0f;
    #pragma unroll
    for (int i = 0; i < 8; i++) { ts += ssum[i]; tq += ssq[i]; }
    float mu   = ts * (1.0f / D_MODEL);
    float var  = tq * (1.0f / D_MODEL) - mu * mu;
    float rstd = rsqrtf(var + 1e-5f);
    float4 scv = *(const float4*)(sc + c);
    float4 biv = *(const float4*)(bi + c);
    float4 o;
    o.x = (r.x - mu) * rstd * scv.x + biv.x;
    o.y = (r.y - mu) * rstd * scv.y + biv.y;
    o.z = (r.z - mu) * rstd * scv.z + biv.z;
    o.w = (r.w - mu) * rstd * scv.w + biv.w;
    *(float4*)(out + (size_t)row * D_MODEL + c) = o;
    __half2* hp = (__half2*)(outh + (size_t)row * D_MODEL + c);
    hp[0] = __floats2half2_rn(o.x, o.y);
    hp[1] = __floats2half2_rn(o.z, o.w);
}

// ---------------- final head ----------------
__global__ void head_kernel(const float* __restrict__ ow, const float* __restrict__ ob,
                            float* __restrict__ out)
{
    int tid = threadIdx.x;           // 128 = 8 batches * 16 actions
    int b = tid >> 4, a = tid & 15;
    const float* hr = g_h + ((size_t)b * SEQ + (SEQ - 1)) * D_MODEL;
    float acc = 0.0f;
    for (int k = 0; k < D_MODEL; k++) acc += hr[k] * ow[k * N_ACTIONS + a];
    acc += ob[a];
    float m = acc;
    #pragma unroll
    for (int o = 8; o > 0; o >>= 1) m = fmaxf(m, __shfl_xor_sync(0xffffffffu, m, o, 16));
    float e = expf(acc - m), sum = e;
    #pragma unroll
    for (int o = 8; o > 0; o >>= 1) sum += __shfl_xor_sync(0xffffffffu, sum, o, 16);
    out[b * N_ACTIONS + a] = acc - m - logf(sum);
}

// ---------------- launch ----------------
extern "C" void kernel_launch(void* const* d_in, const int* in_sizes, int n_in,
                              void* d_out, int out_size)
{
    const int*   x     = (const int*)d_in[0];
    const int*   mask  = (const int*)d_in[1];
    const float* embed = (const float*)d_in[2];
    const float* Wq    = (const float*)d_in[3];
    const float* Wk    = (const float*)d_in[4];
    const float* Wv    = (const float*)d_in[5];
    const float* Wo_w  = (const float*)d_in[6];
    const float* Wo_b  = (const float*)d_in[7];
    const float* ln1s  = (const float*)d_in[8];
    const float* ln1b  = (const float*)d_in[9];
    const float* ffw1  = (const float*)d_in[10];
    const float* ffb1  = (const float*)d_in[11];
    const float* ffw2  = (const float*)d_in[12];
    const float* ffb2  = (const float*)d_in[13];
    const float* ln2s  = (const float*)d_in[14];
    const float* ln2b  = (const float*)d_in[15];
    const float* ow    = (const float*)d_in[16];
    const float* ob    = (const float*)d_in[17];
    float* out = (float*)d_out;

    float *h, *bufa, *bufb;
    __half *h16, *qkv, *ctx, *mid, *wqkv, *wot, *w1t, *w2t;
    cudaGetSymbolAddress((void**)&h,    g_h);
    cudaGetSymbolAddress((void**)&h16,  g_h16);
    cudaGetSymbolAddress((void**)&qkv,  g_qkv);
    cudaGetSymbolAddress((void**)&ctx,  g_ctx);
    cudaGetSymbolAddress((void**)&mid,  g_mid);
    cudaGetSymbolAddress((void**)&bufa, g_bufa);
    cudaGetSymbolAddress((void**)&bufb, g_bufb);
    cudaGetSymbolAddress((void**)&wqkv, g_wqkv);
    cudaGetSymbolAddress((void**)&wot,  g_wot);
    cudaGetSymbolAddress((void**)&w1t,  g_w1t);
    cudaGetSymbolAddress((void**)&w2t,  g_w2t);

    dim3 tb(32, 8);
    // launch order: index 3 = first tgemm (ncu capture target)
    tposeqkv_kernel<<<dim3(2, 32, N_LAYERS * 48), tb>>>(Wq, Wk, Wv);        // 0
    tposew_kernel<<<dim3(32, 32, N_LAYERS), tb>>>(Wo_w, wot, 1024, 1024,
        (size_t)D_MODEL * D_MODEL, (size_t)D_MODEL * D_MODEL);              // 1
    embed_kernel<<<TOK, 256>>>(x, embed);                                   // 2

    for (int i = 0; i < N_LAYERS; i++) {
        tgemm_kernel<<<dim3((3 * D_MODEL) / 128, TOK / 128), 256>>>(        // 3 on i==0
            h16, wqkv + (size_t)i * 3 * D_MODEL * D_MODEL, nullptr,
            nullptr, qkv, TOK, 3 * D_MODEL, D_MODEL, 0);
        attn_kernel<<<dim3(SEQ / AQ, BATCH * N_HEADS), 256>>>(mask);
        if (i == 0) {
            tposew_kernel<<<dim3(128, 32, N_LAYERS), tb>>>(ffw1, w1t, 1024, 4096,
                (size_t)D_MODEL * D_FF, (size_t)D_FF * D_MODEL);
            tposew_kernel<<<dim3(32, 128, N_LAYERS), tb>>>(ffw2, w2t, 4096, 1024,
                (size_t)D_FF * D_MODEL, (size_t)D_MODEL * D_FF);
        }
        tgemm_kernel<<<dim3(D_MODEL / 128, TOK / 128), 256>>>(
            ctx, wot + (size_t)i * D_MODEL * D_MODEL, Wo_b + (size_t)i * D_MODEL,
            bufa, nullptr, TOK, D_MODEL, D_MODEL, 0);
        ln_kernel<<<TOK, 256>>>(h, bufa, ln1s + (size_t)i * D_MODEL, ln1b + (size_t)i * D_MODEL, h, h16);
        tgemm_kernel<<<dim3(D_FF / 128, TOK / 128), 256>>>(
            h16, w1t + (size_t)i * D_FF * D_MODEL, ffb1 + (size_t)i * D_FF,
            nullptr, mid, TOK, D_FF, D_MODEL, FLG_RELU);
        tgemm_kernel<<<dim3(D_MODEL / 128, TOK / 128), 256>>>(
            mid, w2t + (size_t)i * D_MODEL * D_FF, ffb2 + (size_t)i * D_MODEL,
            bufb, nullptr, TOK, D_MODEL, D_FF, 0);
        ln_kernel<<<TOK, 256>>>(h, bufb, ln2s + (size_t)i * D_MODEL, ln2b + (size_t)i * D_MODEL, h, h16);
    }

    head_kernel<<<1, 128>>>(ow, ob, out);
}